// round 15
// baseline (speedup 1.0000x reference)
#include <cuda_runtime.h>
#include <cuda_bf16.h>

// One patch per thread; 16 amplitudes as 8 f32x2 (lane0 = amp m, lane1 = amp 15-m).
// R15 = R14 with a GENTLE register squeeze: natural allocation is 40 regs
// (48-warp/SM ceiling); __launch_bounds__(128,14) caps at 36 regs (56-warp
// ceiling). Unlike R4/R5's failed caps (8-16 regs under the live set), a
// 4-reg squeeze is within ptxas rematerialization range (no LDL/STL spills
// expected — verify L1% stays ~15).
//
// Algebra chain (validated R1-R14, rel_err ~9e-7):
//  * encoding diagonal after H^4, Psi via CSE tree
//  * warp-cooperative uniform weight trig (lane L computes one angle; SHFL
//    broadcast) — 3 MUFU/thread instead of 11
//  * RX butterflies qubits 1,2,3 packed, tangent form (1 fma per output);
//    dropped cos factors deferred into output scale 0.0625*(c1*c2*c3)^2
//  * qubit-0 RX + CNOT-ring Walsh masks {7,12,14,15} folded analytically

typedef unsigned long long u64;

__device__ __forceinline__ u64 pk2(float lo, float hi) {
    u64 r; asm("mov.b64 %0,{%1,%2};" : "=l"(r) : "f"(lo), "f"(hi)); return r;
}
__device__ __forceinline__ void unpk(u64 v, float& lo, float& hi) {
    asm("mov.b64 {%0,%1},%2;" : "=f"(lo), "=f"(hi) : "l"(v));
}
__device__ __forceinline__ u64 fma2(u64 a, u64 b, u64 c) {
    u64 d; asm("fma.rn.f32x2 %0,%1,%2,%3;" : "=l"(d) : "l"(a), "l"(b), "l"(c)); return d;
}

__global__ void __launch_bounds__(128, 14)
qconv_kernel(const float* __restrict__ img,
             const float* __restrict__ wts,
             float* __restrict__ out,
             unsigned int npatch)
{
    unsigned int tid = blockIdx.x * blockDim.x + threadIdx.x;
    if (tid >= npatch) return;

    // ---- warp-cooperative uniform weight trig ----
    unsigned int lane = threadIdx.x & 31u;
    unsigned int wsel = lane & 3u;
    float wl  = __ldg(wts + wsel);
    float ang = wsel ? wl * 0.5f : wl;
    float sl_, cl_;
    __sincosf(ang, &sl_, &cl_);
    float tl = __fdividef(sl_, cl_);
    float sl2 = sl_ + sl_;          // lane 0's value is 2*sin(w0)

    float c0  = __shfl_sync(0xFFFFFFFFu, cl_, 0);
    float s02 = __shfl_sync(0xFFFFFFFFu, sl2, 0);
    float t1  = __shfl_sync(0xFFFFFFFFu, tl, 1);
    float t2  = __shfl_sync(0xFFFFFFFFu, tl, 2);
    float t3  = __shfl_sync(0xFFFFFFFFu, tl, 3);
    float c1  = __shfl_sync(0xFFFFFFFFu, cl_, 1);
    float c2  = __shfl_sync(0xFFFFFFFFu, cl_, 2);
    float c3  = __shfl_sync(0xFFFFFFFFu, cl_, 3);
    float cc  = c1 * c2 * c3;
    float SCL = 0.0625f * cc * cc;
    float twv[3] = { t1, t2, t3 };

    unsigned int b   = tid / 196u;
    unsigned int rem = tid - b * 196u;      // j*14 + k
    unsigned int j   = rem / 14u;
    unsigned int k   = rem - j * 14u;

    const float* base = img + (size_t)b * 784 + (size_t)(2 * j) * 28 + (size_t)(2 * k);
    float2 r0 = *reinterpret_cast<const float2*>(base);       // x0 x1
    float2 r1 = *reinterpret_cast<const float2*>(base + 28);  // x2 x3
    float x0 = r0.x, x1 = r0.y, x2 = r1.x, x3 = r1.y;

    const float HR = 0.3925f;       // 0.785/2
    float h0 = x0 * HR, h1 = x1 * HR, h2 = x2 * HR, h3 = x3 * HR;
    float p01 = h0 * x1, p02 = h0 * x2, p03 = h0 * x3;
    float p12 = h1 * x2, p13 = h1 * x3, p23 = h2 * x3;

    // single-qubit bases S
    float a01 = h0 + h1, b01 = h0 - h1;
    float a23 = h2 + h3, b23 = h2 - h3;
    float SA = a01 + a23, SB = a01 - a23;
    float SC = b01 + a23, SD = b01 - a23;
    float SE = a01 + b23, SF = a01 - b23;
    float SG = b01 + b23, SH = b01 - b23;

    // pair bases P
    float m_ = p12 + p13, n_ = p12 - p13;
    float t_pp = p01 - m_, t_mm = p01 + m_;
    float t_pm = p01 - n_, t_mp = p01 + n_;
    float u_ = p02 + p03, v_ = p02 - p03;
    float q_pp = u_ - p23, q_mm = u_ + p23;
    float q_pm = v_ + p23, q_mp = v_ - p23;

    float P0 = -(t_mm + q_mm);  // m=0: S=SA
    float P1 = -(t_mp + q_mp);  // m=1: S=SE
    float P2 = q_pm - t_pm;     // m=2: S=SF
    float P3 = q_pp - t_pp;     // m=3: S=SB
    float P4 = t_mm - q_mm;     // m=4: S=SC
    float P5 = t_mp - q_mp;     // m=5: S=SG
    float P6 = t_pm + q_pm;     // m=6: S=SH
    float P7 = t_pp + q_pp;     // m=7: S=SD

    float Sv[8] = { SA, SE, SF, SB, SC, SG, SH, SD };
    float Pv[8] = { P0, P1, P2, P3, P4, P5, P6, P7 };

    // packed amplitudes: lane0 = e^{i(P-S)}, lane1 = e^{i(P+S)}
    u64 AR[8], AI[8];
#pragma unroll
    for (int m = 0; m < 8; ++m) {
        float lo = Pv[m] - Sv[m];
        float hi = Pv[m] + Sv[m];
        float sl, cl, sh, ch;
        __sincosf(lo, &sl, &cl);
        __sincosf(hi, &sh, &ch);
        AR[m] = pk2(cl, ch);
        AI[m] = pk2(sl, sh);
    }

    // RX butterflies qubits 1,2,3 (bits 4,2,1), tangent form: 1 fma per output.
#pragma unroll
    for (int q = 0; q < 3; ++q) {
        float tw = twv[q];
        u64 tw2p = pk2(tw, tw), ntw2p = pk2(-tw, -tw);
        int bit = 4 >> q;               // 4, 2, 1
#pragma unroll
        for (int m = 0; m < 8; ++m) {
            if (m & bit) continue;
            int t = m | bit;
            u64 a0r = AR[m], a0i = AI[m];
            u64 a1r = AR[t], a1i = AI[t];
            AR[m] = fma2(tw2p,  a1i, a0r);   // a0r + tw*a1i
            AI[m] = fma2(ntw2p, a1r, a0i);   // a0i - tw*a1r
            AR[t] = fma2(tw2p,  a0i, a1r);   // a1r + tw*a0i
            AI[t] = fma2(ntw2p, a0r, a1i);   // a1i - tw*a0r
        }
    }

    // qubit-0 fold (scalar): pair (s, s+8) = (lane0 reg s, lane1 reg 7-s)
    float SUM[8], DIF[8];
#pragma unroll
    for (int s = 0; s < 4; ++s) {
        int r7 = 7 - s;
        float arl, arh, ail, aih;       // reg s
        float brl, brh, bil, bih;       // reg 7-s
        unpk(AR[s],  arl, arh);
        unpk(AI[s],  ail, aih);
        unpk(AR[r7], brl, brh);
        unpk(AI[r7], bil, bih);

        {   // pair s: a_s = (arl, ail), a_{s+8} = (brh, bih)
            float Ns = arl * arl + ail * ail;
            float Nt = brh * brh + bih * bih;
            float Cx = arl * bih - ail * brh;
            SUM[s] = Ns + Nt;
            DIF[s] = c0 * (Ns - Nt) + s02 * Cx;
        }
        {   // pair 7-s: a_{7-s} = (brl, bil), a_{15-s} = (arh, aih)
            float Ns = brl * brl + bil * bil;
            float Nt = arh * arh + aih * aih;
            float Cx = brl * aih - bil * arh;
            SUM[r7] = Ns + Nt;
            DIF[r7] = c0 * (Ns - Nt) + s02 * Cx;
        }
    }

    // Walsh trees over s = 4*b1 + 2*b2 + b3
    float d0 = DIF[0] - DIF[1], d1 = DIF[2] - DIF[3];
    float d2 = DIF[4] - DIF[5], d3 = DIF[6] - DIF[7];
    float e0 = DIF[0] + DIF[1], e1 = DIF[2] + DIF[3];
    float e2 = DIF[4] + DIF[5], e3 = DIF[6] + DIF[7];

    float E15 = (d0 - d1) - (d2 - d3);
    float E14 = (e0 - e1) - (e2 - e3);
    float E12 = (e0 + e1) - (e2 + e3);

    float w0_ = SUM[0] - SUM[1], w1_ = SUM[2] - SUM[3];
    float w2_ = SUM[4] - SUM[5], w3_ = SUM[6] - SUM[7];
    float E7 = (w0_ - w1_) - (w2_ - w3_);

    // output (B,4,14,14), channels [Z3,Z2,Z1,Z0]; SCL = 0.0625*(c1c2c3)^2
    float* o = out + (size_t)b * 784 + rem;
    o[0]   = E15 * SCL;   // Z3 (mask 15)
    o[196] = E14 * SCL;   // Z2 (mask 14)
    o[392] = E12 * SCL;   // Z1 (mask 12)
    o[588] = E7  * SCL;   // Z0 (mask 7)
}

extern "C" void kernel_launch(void* const* d_in, const int* in_sizes, int n_in,
                              void* d_out, int out_size) {
    const float* img = (const float*)d_in[0];
    const float* wts = (const float*)d_in[1];
    float* out = (float*)d_out;

    unsigned int B = (unsigned int)(in_sizes[0] / 784);
    unsigned int npatch = B * 196u;

    unsigned int threads = 128;
    unsigned int blocks = (npatch + threads - 1) / threads;
    qconv_kernel<<<blocks, threads>>>(img, wts, out, npatch);
}

// round 16
// speedup vs baseline: 1.2548x; 1.2548x over previous
#include <cuda_runtime.h>
#include <cuda_bf16.h>

// One patch per thread; 16 amplitudes as 8 f32x2 (lane0 = amp m, lane1 = amp 15-m).
// R16 = R13 (best: bench 14.75, kernel 12.67) + micro-trims:
//   * 96-thread blocks (3-warp granularity packs the regfile to a 51-warp/SM
//     ceiling vs 48 for 2-warp blocks)
//   * pixel loads issued before the weight-trig MUFU chain (hide LDG latency)
//   * no reg caps (R4/R5/R15 all proved caps below the ~40-reg natural
//     allocation convert directly into spills)
//
// Algebra chain (validated R1-R15, rel_err ~9e-7):
//  * encoding diagonal after H^4, Psi via CSE tree
//  * warp-cooperative uniform weight trig (lane L computes one angle; SHFL
//    broadcast) — 3 MUFU instrs/warp instead of 11
//  * RX butterflies qubits 1,2,3 packed, tangent form (1 fma per output);
//    dropped cos factors deferred into output scale 0.0625*(c1*c2*c3)^2
//  * qubit-0 RX + CNOT-ring Walsh masks {7,12,14,15} folded analytically

typedef unsigned long long u64;

__device__ __forceinline__ u64 pk2(float lo, float hi) {
    u64 r; asm("mov.b64 %0,{%1,%2};" : "=l"(r) : "f"(lo), "f"(hi)); return r;
}
__device__ __forceinline__ void unpk(u64 v, float& lo, float& hi) {
    asm("mov.b64 {%0,%1},%2;" : "=f"(lo), "=f"(hi) : "l"(v));
}
__device__ __forceinline__ u64 fma2(u64 a, u64 b, u64 c) {
    u64 d; asm("fma.rn.f32x2 %0,%1,%2,%3;" : "=l"(d) : "l"(a), "l"(b), "l"(c)); return d;
}

__global__ void __launch_bounds__(96)
qconv_kernel(const float* __restrict__ img,
             const float* __restrict__ wts,
             float* __restrict__ out,
             unsigned int npatch)
{
    unsigned int tid = blockIdx.x * blockDim.x + threadIdx.x;
    if (tid >= npatch) return;

    // ---- index math + pixel loads FIRST (LDG latency hides under trig) ----
    unsigned int b   = tid / 196u;
    unsigned int rem = tid - b * 196u;      // j*14 + k
    unsigned int j   = rem / 14u;
    unsigned int k   = rem - j * 14u;

    const float* base = img + (size_t)b * 784 + (size_t)(2 * j) * 28 + (size_t)(2 * k);
    float2 r0 = *reinterpret_cast<const float2*>(base);       // x0 x1
    float2 r1 = *reinterpret_cast<const float2*>(base + 28);  // x2 x3

    // ---- warp-cooperative uniform weight trig ----
    unsigned int lane = threadIdx.x & 31u;
    unsigned int wsel = lane & 3u;
    float wl  = __ldg(wts + wsel);
    float ang = wsel ? wl * 0.5f : wl;
    float sl_, cl_;
    __sincosf(ang, &sl_, &cl_);
    float tl  = __fdividef(sl_, cl_);
    float sl2 = sl_ + sl_;          // lane 0 holds 2*sin(w0)

    float c0  = __shfl_sync(0xFFFFFFFFu, cl_, 0);
    float s02 = __shfl_sync(0xFFFFFFFFu, sl2, 0);
    float t1  = __shfl_sync(0xFFFFFFFFu, tl, 1);
    float t2  = __shfl_sync(0xFFFFFFFFu, tl, 2);
    float t3  = __shfl_sync(0xFFFFFFFFu, tl, 3);
    float c1  = __shfl_sync(0xFFFFFFFFu, cl_, 1);
    float c2  = __shfl_sync(0xFFFFFFFFu, cl_, 2);
    float c3  = __shfl_sync(0xFFFFFFFFu, cl_, 3);
    float cc  = c1 * c2 * c3;
    float SCL = 0.0625f * cc * cc;

    float x0 = r0.x, x1 = r0.y, x2 = r1.x, x3 = r1.y;

    const float HR = 0.3925f;       // 0.785/2
    float h0 = x0 * HR, h1 = x1 * HR, h2 = x2 * HR, h3 = x3 * HR;
    float p01 = h0 * x1, p02 = h0 * x2, p03 = h0 * x3;
    float p12 = h1 * x2, p13 = h1 * x3, p23 = h2 * x3;

    // single-qubit bases S
    float a01 = h0 + h1, b01 = h0 - h1;
    float a23 = h2 + h3, b23 = h2 - h3;
    float SA = a01 + a23, SB = a01 - a23;
    float SC = b01 + a23, SD = b01 - a23;
    float SE = a01 + b23, SF = a01 - b23;
    float SG = b01 + b23, SH = b01 - b23;

    // pair bases P
    float m_ = p12 + p13, n_ = p12 - p13;
    float t_pp = p01 - m_, t_mm = p01 + m_;
    float t_pm = p01 - n_, t_mp = p01 + n_;
    float u_ = p02 + p03, v_ = p02 - p03;
    float q_pp = u_ - p23, q_mm = u_ + p23;
    float q_pm = v_ + p23, q_mp = v_ - p23;

    float P0 = -(t_mm + q_mm);  // m=0: S=SA
    float P1 = -(t_mp + q_mp);  // m=1: S=SE
    float P2 = q_pm - t_pm;     // m=2: S=SF
    float P3 = q_pp - t_pp;     // m=3: S=SB
    float P4 = t_mm - q_mm;     // m=4: S=SC
    float P5 = t_mp - q_mp;     // m=5: S=SG
    float P6 = t_pm + q_pm;     // m=6: S=SH
    float P7 = t_pp + q_pp;     // m=7: S=SD

    float Sv[8] = { SA, SE, SF, SB, SC, SG, SH, SD };
    float Pv[8] = { P0, P1, P2, P3, P4, P5, P6, P7 };

    // packed amplitudes: lane0 = e^{i(P-S)}, lane1 = e^{i(P+S)}
    u64 AR[8], AI[8];
#pragma unroll
    for (int m = 0; m < 8; ++m) {
        float lo = Pv[m] - Sv[m];
        float hi = Pv[m] + Sv[m];
        float sl, cl, sh, ch;
        __sincosf(lo, &sl, &cl);
        __sincosf(hi, &sh, &ch);
        AR[m] = pk2(cl, ch);
        AI[m] = pk2(sl, sh);
    }

    // RX butterflies qubits 1,2,3 (bits 4,2,1), tangent form: 1 fma per output.
#pragma unroll
    for (int q = 0; q < 3; ++q) {
        float tw = (q == 0) ? t1 : (q == 1) ? t2 : t3;
        u64 tw2p = pk2(tw, tw), ntw2p = pk2(-tw, -tw);
        int bit = 4 >> q;               // 4, 2, 1
#pragma unroll
        for (int m = 0; m < 8; ++m) {
            if (m & bit) continue;
            int t = m | bit;
            u64 a0r = AR[m], a0i = AI[m];
            u64 a1r = AR[t], a1i = AI[t];
            AR[m] = fma2(tw2p,  a1i, a0r);   // a0r + tw*a1i
            AI[m] = fma2(ntw2p, a1r, a0i);   // a0i - tw*a1r
            AR[t] = fma2(tw2p,  a0i, a1r);   // a1r + tw*a0i
            AI[t] = fma2(ntw2p, a0r, a1i);   // a1i - tw*a0r
        }
    }

    // qubit-0 fold (scalar): pair (s, s+8) = (lane0 reg s, lane1 reg 7-s)
    float SUM[8], DIF[8];
#pragma unroll
    for (int s = 0; s < 4; ++s) {
        int r7 = 7 - s;
        float arl, arh, ail, aih;       // reg s
        float brl, brh, bil, bih;       // reg 7-s
        unpk(AR[s],  arl, arh);
        unpk(AI[s],  ail, aih);
        unpk(AR[r7], brl, brh);
        unpk(AI[r7], bil, bih);

        {   // pair s: a_s = (arl, ail), a_{s+8} = (brh, bih)
            float Ns = arl * arl + ail * ail;
            float Nt = brh * brh + bih * bih;
            float Cx = arl * bih - ail * brh;
            SUM[s] = Ns + Nt;
            DIF[s] = c0 * (Ns - Nt) + s02 * Cx;
        }
        {   // pair 7-s: a_{7-s} = (brl, bil), a_{15-s} = (arh, aih)
            float Ns = brl * brl + bil * bil;
            float Nt = arh * arh + aih * aih;
            float Cx = brl * aih - bil * arh;
            SUM[r7] = Ns + Nt;
            DIF[r7] = c0 * (Ns - Nt) + s02 * Cx;
        }
    }

    // Walsh trees over s = 4*b1 + 2*b2 + b3
    float d0 = DIF[0] - DIF[1], d1 = DIF[2] - DIF[3];
    float d2 = DIF[4] - DIF[5], d3 = DIF[6] - DIF[7];
    float e0 = DIF[0] + DIF[1], e1 = DIF[2] + DIF[3];
    float e2 = DIF[4] + DIF[5], e3 = DIF[6] + DIF[7];

    float E15 = (d0 - d1) - (d2 - d3);
    float E14 = (e0 - e1) - (e2 - e3);
    float E12 = (e0 + e1) - (e2 + e3);

    float w0_ = SUM[0] - SUM[1], w1_ = SUM[2] - SUM[3];
    float w2_ = SUM[4] - SUM[5], w3_ = SUM[6] - SUM[7];
    float E7 = (w0_ - w1_) - (w2_ - w3_);

    // output (B,4,14,14), channels [Z3,Z2,Z1,Z0]; SCL = 0.0625*(c1c2c3)^2
    float* o = out + (size_t)b * 784 + rem;
    o[0]   = E15 * SCL;   // Z3 (mask 15)
    o[196] = E14 * SCL;   // Z2 (mask 14)
    o[392] = E12 * SCL;   // Z1 (mask 12)
    o[588] = E7  * SCL;   // Z0 (mask 7)
}

extern "C" void kernel_launch(void* const* d_in, const int* in_sizes, int n_in,
                              void* d_out, int out_size) {
    const float* img = (const float*)d_in[0];
    const float* wts = (const float*)d_in[1];
    float* out = (float*)d_out;

    unsigned int B = (unsigned int)(in_sizes[0] / 784);
    unsigned int npatch = B * 196u;

    unsigned int threads = 96;
    unsigned int blocks = (npatch + threads - 1) / threads;
    qconv_kernel<<<blocks, threads>>>(img, wts, out, npatch);
}

// round 17
// speedup vs baseline: 1.2989x; 1.0352x over previous
#include <cuda_runtime.h>
#include <cuda_bf16.h>

// One patch per thread; 16 amplitudes as 8 f32x2 (lane0 = amp m, lane1 = amp 15-m).
// R17 = R13 (best) + packed-norm fold: all 16 |a|^2 computed as 8 packed
// square-fmas (NP[s] = (N_s, N_{15-s})), replacing 32 scalar ops; SUM/ND are
// scalar lane combos (no lane-swap movs — the R8 failure). Block = 64 (R13's
// proven config). No reg caps (R4/R5/R15 proved caps below ~40 regs spill).
//
// Algebra chain (validated R1-R16, rel_err ~9e-7):
//  * encoding diagonal after H^4, Psi via CSE tree
//  * warp-cooperative uniform weight trig (lane L computes one angle; SHFL)
//  * RX butterflies qubits 1,2,3 packed, tangent form; cos factors deferred
//    into output scale 0.0625*(c1*c2*c3)^2
//  * qubit-0 RX + CNOT-ring Walsh masks {7,12,14,15} folded analytically

typedef unsigned long long u64;

__device__ __forceinline__ u64 pk2(float lo, float hi) {
    u64 r; asm("mov.b64 %0,{%1,%2};" : "=l"(r) : "f"(lo), "f"(hi)); return r;
}
__device__ __forceinline__ void unpk(u64 v, float& lo, float& hi) {
    asm("mov.b64 {%0,%1},%2;" : "=f"(lo), "=f"(hi) : "l"(v));
}
__device__ __forceinline__ u64 mul2(u64 a, u64 b) {
    u64 d; asm("mul.rn.f32x2 %0,%1,%2;" : "=l"(d) : "l"(a), "l"(b)); return d;
}
__device__ __forceinline__ u64 fma2(u64 a, u64 b, u64 c) {
    u64 d; asm("fma.rn.f32x2 %0,%1,%2,%3;" : "=l"(d) : "l"(a), "l"(b), "l"(c)); return d;
}

__global__ void __launch_bounds__(64)
qconv_kernel(const float* __restrict__ img,
             const float* __restrict__ wts,
             float* __restrict__ out,
             unsigned int npatch)
{
    unsigned int tid = blockIdx.x * blockDim.x + threadIdx.x;
    if (tid >= npatch) return;

    // ---- index math + pixel loads first (LDG hides under trig) ----
    unsigned int b   = tid / 196u;
    unsigned int rem = tid - b * 196u;      // j*14 + k
    unsigned int j   = rem / 14u;
    unsigned int k   = rem - j * 14u;

    const float* base = img + (size_t)b * 784 + (size_t)(2 * j) * 28 + (size_t)(2 * k);
    float2 r0 = *reinterpret_cast<const float2*>(base);       // x0 x1
    float2 r1 = *reinterpret_cast<const float2*>(base + 28);  // x2 x3

    // ---- warp-cooperative uniform weight trig ----
    unsigned int lane = threadIdx.x & 31u;
    unsigned int wsel = lane & 3u;
    float wl  = __ldg(wts + wsel);
    float ang = wsel ? wl * 0.5f : wl;
    float sl_, cl_;
    __sincosf(ang, &sl_, &cl_);
    float tl  = __fdividef(sl_, cl_);
    float sl2 = sl_ + sl_;          // lane 0 holds 2*sin(w0)

    float c0  = __shfl_sync(0xFFFFFFFFu, cl_, 0);
    float s02 = __shfl_sync(0xFFFFFFFFu, sl2, 0);
    float t1  = __shfl_sync(0xFFFFFFFFu, tl, 1);
    float t2  = __shfl_sync(0xFFFFFFFFu, tl, 2);
    float t3  = __shfl_sync(0xFFFFFFFFu, tl, 3);
    float c1  = __shfl_sync(0xFFFFFFFFu, cl_, 1);
    float c2  = __shfl_sync(0xFFFFFFFFu, cl_, 2);
    float c3  = __shfl_sync(0xFFFFFFFFu, cl_, 3);
    float cc  = c1 * c2 * c3;
    float SCL = 0.0625f * cc * cc;

    float x0 = r0.x, x1 = r0.y, x2 = r1.x, x3 = r1.y;

    const float HR = 0.3925f;       // 0.785/2
    float h0 = x0 * HR, h1 = x1 * HR, h2 = x2 * HR, h3 = x3 * HR;
    float p01 = h0 * x1, p02 = h0 * x2, p03 = h0 * x3;
    float p12 = h1 * x2, p13 = h1 * x3, p23 = h2 * x3;

    // single-qubit bases S
    float a01 = h0 + h1, b01 = h0 - h1;
    float a23 = h2 + h3, b23 = h2 - h3;
    float SA = a01 + a23, SB = a01 - a23;
    float SC = b01 + a23, SD = b01 - a23;
    float SE = a01 + b23, SF = a01 - b23;
    float SG = b01 + b23, SH = b01 - b23;

    // pair bases P
    float m_ = p12 + p13, n_ = p12 - p13;
    float t_pp = p01 - m_, t_mm = p01 + m_;
    float t_pm = p01 - n_, t_mp = p01 + n_;
    float u_ = p02 + p03, v_ = p02 - p03;
    float q_pp = u_ - p23, q_mm = u_ + p23;
    float q_pm = v_ + p23, q_mp = v_ - p23;

    float P0 = -(t_mm + q_mm);  // m=0: S=SA
    float P1 = -(t_mp + q_mp);  // m=1: S=SE
    float P2 = q_pm - t_pm;     // m=2: S=SF
    float P3 = q_pp - t_pp;     // m=3: S=SB
    float P4 = t_mm - q_mm;     // m=4: S=SC
    float P5 = t_mp - q_mp;     // m=5: S=SG
    float P6 = t_pm + q_pm;     // m=6: S=SH
    float P7 = t_pp + q_pp;     // m=7: S=SD

    float Sv[8] = { SA, SE, SF, SB, SC, SG, SH, SD };
    float Pv[8] = { P0, P1, P2, P3, P4, P5, P6, P7 };

    // packed amplitudes: lane0 = e^{i(P-S)}, lane1 = e^{i(P+S)}
    u64 AR[8], AI[8];
#pragma unroll
    for (int m = 0; m < 8; ++m) {
        float lo = Pv[m] - Sv[m];
        float hi = Pv[m] + Sv[m];
        float sl, cl, sh, ch;
        __sincosf(lo, &sl, &cl);
        __sincosf(hi, &sh, &ch);
        AR[m] = pk2(cl, ch);
        AI[m] = pk2(sl, sh);
    }

    // RX butterflies qubits 1,2,3 (bits 4,2,1), tangent form: 1 fma per output.
#pragma unroll
    for (int q = 0; q < 3; ++q) {
        float tw = (q == 0) ? t1 : (q == 1) ? t2 : t3;
        u64 tw2p = pk2(tw, tw), ntw2p = pk2(-tw, -tw);
        int bit = 4 >> q;               // 4, 2, 1
#pragma unroll
        for (int m = 0; m < 8; ++m) {
            if (m & bit) continue;
            int t = m | bit;
            u64 a0r = AR[m], a0i = AI[m];
            u64 a1r = AR[t], a1i = AI[t];
            AR[m] = fma2(tw2p,  a1i, a0r);   // a0r + tw*a1i
            AI[m] = fma2(ntw2p, a1r, a0i);   // a0i - tw*a1r
            AR[t] = fma2(tw2p,  a0i, a1r);   // a1r + tw*a0i
            AI[t] = fma2(ntw2p, a0r, a1i);   // a1i - tw*a0r
        }
    }

    // ---- packed norms: NP[s] = (N_s, N_{15-s}) — 16 packed slots for 16 |a|^2
    float Nlo[8], Nhi[8];
#pragma unroll
    for (int s = 0; s < 8; ++s) {
        u64 NP = fma2(AI[s], AI[s], mul2(AR[s], AR[s]));
        unpk(NP, Nlo[s], Nhi[s]);       // N[s] = Nlo[s], N[15-s] = Nhi[s]
    }

    // ---- qubit-0 fold (scalar combos; amp s+8 = lane1 of reg 7-s) ----
    float SUM[8], DIF[8];
#pragma unroll
    for (int s = 0; s < 8; ++s) {
        int r7 = 7 - s;
        float arl, arh, ail, aih;
        unpk(AR[s],  arl, arh);  (void)arh;
        unpk(AI[s],  ail, aih);  (void)aih;
        float brh, bih, brl, bil;
        unpk(AR[r7], brl, brh);  (void)brl;
        unpk(AI[r7], bil, bih);  (void)bil;

        float Ns = Nlo[s];              // N_s
        float Nt = Nhi[r7];             // N_{s+8} = N_{15-(7-s)}
        float Cx = arl * bih - ail * brh;   // Im(a_s* a_{s+8})
        SUM[s] = Ns + Nt;
        DIF[s] = c0 * (Ns - Nt) + s02 * Cx;
    }

    // Walsh trees over s = 4*b1 + 2*b2 + b3
    float d0 = DIF[0] - DIF[1], d1 = DIF[2] - DIF[3];
    float d2 = DIF[4] - DIF[5], d3 = DIF[6] - DIF[7];
    float e0 = DIF[0] + DIF[1], e1 = DIF[2] + DIF[3];
    float e2 = DIF[4] + DIF[5], e3 = DIF[6] + DIF[7];

    float E15 = (d0 - d1) - (d2 - d3);
    float E14 = (e0 - e1) - (e2 - e3);
    float E12 = (e0 + e1) - (e2 + e3);

    float w0_ = SUM[0] - SUM[1], w1_ = SUM[2] - SUM[3];
    float w2_ = SUM[4] - SUM[5], w3_ = SUM[6] - SUM[7];
    float E7 = (w0_ - w1_) - (w2_ - w3_);

    // output (B,4,14,14), channels [Z3,Z2,Z1,Z0]; SCL = 0.0625*(c1c2c3)^2
    float* o = out + (size_t)b * 784 + rem;
    o[0]   = E15 * SCL;   // Z3 (mask 15)
    o[196] = E14 * SCL;   // Z2 (mask 14)
    o[392] = E12 * SCL;   // Z1 (mask 12)
    o[588] = E7  * SCL;   // Z0 (mask 7)
}

extern "C" void kernel_launch(void* const* d_in, const int* in_sizes, int n_in,
                              void* d_out, int out_size) {
    const float* img = (const float*)d_in[0];
    const float* wts = (const float*)d_in[1];
    float* out = (float*)d_out;

    unsigned int B = (unsigned int)(in_sizes[0] / 784);
    unsigned int npatch = B * 196u;

    unsigned int threads = 64;
    unsigned int blocks = (npatch + threads - 1) / threads;
    qconv_kernel<<<blocks, threads>>>(img, wts, out, npatch);
}